// round 7
// baseline (speedup 1.0000x reference)
#include <cuda_runtime.h>
#include <cuda_bf16.h>
#include <math.h>

#define EPSV 0.0001f
#define SEQ  2304
#define KT   128           // attention key tile
#define KS_STR 20          // Ks row stride (words): 16 data + 4 pad
#define VS_STR 68          // Vs row stride (words): 64 keypairs + 4 pad
#define TILE_WORDS (KT * KS_STR + 32 * VS_STR)   // 4736 words per buffer
#define KBYTES (KT * KS_STR * 4)                 // K tile bytes: 10240
#define NTILES (SEQ / KT)                        // 18

// ---------------- scratch (device globals) ------------------------------------
__device__ float    g_wqkv[768 * 256];
__device__ float    g_wout[256 * 256];
__device__ float    g_y[2 * 768 * SEQ];
__device__ unsigned g_qkvh[2 * 8 * 3 * SEQ * 16];   // bf16x2 words (Q pre-scaled, K)
__device__ unsigned g_vTw[16 * 32 * (SEQ / 2)];     // V transposed: [nh][ch][s] bf16
__device__ float    g_att[2 * 256 * SEQ];

// ---------------- helpers ------------------------------------------------------
__device__ __forceinline__ unsigned pack_bf(float lo, float hi) {
    unsigned r;
    asm("cvt.rn.bf16x2.f32 %0, %1, %2;" : "=r"(r) : "f"(hi), "f"(lo));
    return r;
}
__device__ __forceinline__ unsigned ex2_bf16x2(unsigned x) {
    unsigned r;
    asm("ex2.approx.ftz.bf16x2 %0, %1;" : "=r"(r) : "r"(x));
    return r;
}
__device__ __forceinline__ void mma_tf32(float c[4],
                                         unsigned a0, unsigned a1, unsigned a2, unsigned a3,
                                         unsigned b0, unsigned b1) {
    asm volatile("mma.sync.aligned.m16n8k8.row.col.f32.tf32.tf32.f32 "
                 "{%0,%1,%2,%3}, {%4,%5,%6,%7}, {%8,%9}, {%0,%1,%2,%3};"
                 : "+f"(c[0]), "+f"(c[1]), "+f"(c[2]), "+f"(c[3])
                 : "r"(a0), "r"(a1), "r"(a2), "r"(a3), "r"(b0), "r"(b1));
}
__device__ __forceinline__ void mma_bf16(float c[4],
                                         unsigned a0, unsigned a1, unsigned a2, unsigned a3,
                                         unsigned b0, unsigned b1) {
    asm volatile("mma.sync.aligned.m16n8k16.row.col.f32.bf16.bf16.f32 "
                 "{%0,%1,%2,%3}, {%4,%5,%6,%7}, {%8,%9}, {%0,%1,%2,%3};"
                 : "+f"(c[0]), "+f"(c[1]), "+f"(c[2]), "+f"(c[3])
                 : "r"(a0), "r"(a1), "r"(a2), "r"(a3), "r"(b0), "r"(b1));
}
__device__ __forceinline__ void ldsm_x4(unsigned r[4], unsigned addr) {
    asm volatile("ldmatrix.sync.aligned.m8n8.x4.shared.b16 {%0,%1,%2,%3}, [%4];"
                 : "=r"(r[0]), "=r"(r[1]), "=r"(r[2]), "=r"(r[3]) : "r"(addr));
}
__device__ __forceinline__ void cpa16(unsigned saddr, const void* g) {
    asm volatile("cp.async.cg.shared.global [%0], [%1], 16;" :: "r"(saddr), "l"(g));
}
__device__ __forceinline__ void cpa_commit() {
    asm volatile("cp.async.commit_group;");
}
__device__ __forceinline__ void cpa_wait1() {
    asm volatile("cp.async.wait_group 1;");
}

// ---------------- weight normalization ----------------------------------------
__global__ void norm_w_kernel(const float* __restrict__ w_qkv,
                              const float* __restrict__ w_out) {
    __shared__ float red[256];
    const int row = blockIdx.x;
    const int t = threadIdx.x;
    const float* src;
    float* dst;
    int r;
    if (row < 768) { src = w_qkv; dst = g_wqkv; r = row; }
    else           { src = w_out; dst = g_wout; r = row - 768; }
    float v = src[r * 256 + t];
    red[t] = v * v;
    __syncthreads();
    #pragma unroll
    for (int s = 128; s > 0; s >>= 1) {
        if (t < s) red[t] += red[t + s];
        __syncthreads();
    }
    float norm = EPSV + sqrtf(red[0]) * 0.0625f;
    dst[r * 256 + t] = v / (norm * 16.0f);
}

// ---------------- tf32 mma GEMM: C[M,2304] = A[M,256] * B[256,2304] -----------
template <bool RES>
__device__ __forceinline__ void gemm_mma_body(const float* __restrict__ A,
                                              const float* __restrict__ B,
                                              float* __restrict__ C,
                                              const float* __restrict__ X) {
    __shared__ unsigned As[64 * 36];
    __shared__ unsigned Bs[32 * 72];
    const int tid = threadIdx.x;
    const int lane = tid & 31;
    const int wid = tid >> 5;
    const int wm = wid & 3, wn = wid >> 2;
    const int gi = lane >> 2, qi = lane & 3;
    const int rowb = blockIdx.y * 64;
    const int colb = blockIdx.x * 64;

    float acc[4][4];
    #pragma unroll
    for (int i = 0; i < 4; i++)
        #pragma unroll
        for (int j = 0; j < 4; j++) acc[i][j] = 0.0f;

    const int am = tid >> 2, akq = tid & 3;
    const int bk = tid >> 4, bn4 = tid & 15;

    for (int k0 = 0; k0 < 256; k0 += 32) {
        uint4 a0 = *(const uint4*)&A[(rowb + am) * 256 + k0 + 4 * akq];
        uint4 a1 = *(const uint4*)&A[(rowb + am) * 256 + k0 + 16 + 4 * akq];
        *(uint4*)&As[am * 36 + 4 * akq] = a0;
        *(uint4*)&As[am * 36 + 16 + 4 * akq] = a1;
        uint4 b0 = *(const uint4*)&B[(size_t)(k0 + 2 * bk) * SEQ + colb + 4 * bn4];
        uint4 b1 = *(const uint4*)&B[(size_t)(k0 + 2 * bk + 1) * SEQ + colb + 4 * bn4];
        *(uint4*)&Bs[(2 * bk) * 72 + 4 * bn4] = b0;
        *(uint4*)&Bs[(2 * bk + 1) * 72 + 4 * bn4] = b1;
        __syncthreads();

        #pragma unroll
        for (int ks = 0; ks < 4; ks++) {
            const int mrow = wm * 16 + gi;
            unsigned fa0 = As[mrow * 36 + ks * 8 + qi];
            unsigned fa1 = As[(mrow + 8) * 36 + ks * 8 + qi];
            unsigned fa2 = As[mrow * 36 + ks * 8 + qi + 4];
            unsigned fa3 = As[(mrow + 8) * 36 + ks * 8 + qi + 4];
            #pragma unroll
            for (int nb = 0; nb < 4; nb++) {
                unsigned fb0 = Bs[(ks * 8 + qi) * 72 + wn * 32 + nb * 8 + gi];
                unsigned fb1 = Bs[(ks * 8 + qi + 4) * 72 + wn * 32 + nb * 8 + gi];
                mma_tf32(acc[nb], fa0, fa1, fa2, fa3, fb0, fb1);
            }
        }
        __syncthreads();
    }

    const float CA = 0.9191450300180578f;   // 0.7/sqrt(0.58)
    const float CB = 0.3939192985791676f;   // 0.3/sqrt(0.58)
    const int rg0 = rowb + wm * 16 + gi;
    const int rg1 = rg0 + 8;
    #pragma unroll
    for (int nb = 0; nb < 4; nb++) {
        const int col = colb + wn * 32 + nb * 8 + 2 * qi;
        float2 r0, r1;
        if (RES) {
            float2 x0 = *(const float2*)&X[(size_t)rg0 * SEQ + col];
            float2 x1 = *(const float2*)&X[(size_t)rg1 * SEQ + col];
            r0.x = CA * x0.x + CB * acc[nb][0];
            r0.y = CA * x0.y + CB * acc[nb][1];
            r1.x = CA * x1.x + CB * acc[nb][2];
            r1.y = CA * x1.y + CB * acc[nb][3];
        } else {
            r0.x = acc[nb][0]; r0.y = acc[nb][1];
            r1.x = acc[nb][2]; r1.y = acc[nb][3];
        }
        *(float2*)&C[(size_t)rg0 * SEQ + col] = r0;
        *(float2*)&C[(size_t)rg1 * SEQ + col] = r1;
    }
}

__global__ void gemm_qkv_kernel(const float* __restrict__ x) {
    const int n = blockIdx.z;
    gemm_mma_body<false>(g_wqkv, x + (size_t)n * 256 * SEQ,
                         g_y + (size_t)n * 768 * SEQ, nullptr);
}
__global__ void gemm_out_kernel(float* __restrict__ out, const float* __restrict__ x) {
    const int n = blockIdx.z;
    gemm_mma_body<true>(g_wout, g_att + (size_t)n * 256 * SEQ,
                        out + (size_t)n * 256 * SEQ, x + (size_t)n * 256 * SEQ);
}

// ---------------- per-position 32-dim normalization -> bf16 -------------------
__global__ void norm_qkv_kernel() {
    int g = blockIdx.x * blockDim.x + threadIdx.x;   // over 2 * n*8*3*2304
    const int half = g & 1;
    const int idx = g >> 1;
    int s = idx % SEQ;
    int r = idx / SEQ;
    int tq = r % 3; r /= 3;
    int h = r % 8;
    int n = r / 8;
    const float* base = g_y + ((size_t)n * 768 + h * 96 + tq) * SEQ + s
                        + (size_t)half * 16 * 3 * SEQ;
    float v[16];
    float ss = 0.0f;
    #pragma unroll
    for (int c = 0; c < 16; c++) {
        float xv = base[(size_t)c * 3 * SEQ];
        v[c] = xv;
        ss += xv * xv;
    }
    ss += __shfl_xor_sync(0xFFFFFFFFu, ss, 1);
    float inv = 1.0f / (EPSV + sqrtf(ss) * 0.17677669529663687f);
    if (tq == 0) inv *= 0.25503372121867511f;       // 1/(sqrt(32)*ln2)

    if (tq == 2) {
        unsigned short* vh = (unsigned short*)g_vTw;
        size_t ob = ((size_t)(n * 8 + h) * 32 + half * 16) * SEQ + s;
        #pragma unroll
        for (int c = 0; c < 16; c++) {
            __nv_bfloat16 b = __float2bfloat16(v[c] * inv);
            vh[ob + (size_t)c * SEQ] = *(unsigned short*)&b;
        }
    } else {
        unsigned w[8];
        #pragma unroll
        for (int c = 0; c < 8; c++)
            w[c] = pack_bf(v[2 * c] * inv, v[2 * c + 1] * inv);
        uint4* dst = (uint4*)(g_qkvh + (size_t)idx * 16 + half * 8);
        dst[0] = make_uint4(w[0], w[1], w[2], w[3]);
        dst[1] = make_uint4(w[4], w[5], w[6], w[7]);
    }
}

// ---------------- bf16 flash attention: staggered chunks + bf16x2 ex2 ----------
__global__ void __launch_bounds__(256, 2) attn_kernel() {
    __shared__ __align__(16) unsigned sm[2][TILE_WORDS];

    const int nh = blockIdx.y;
    const int qbase = blockIdx.x * 128;
    const int tid = threadIdx.x;
    const int wid = tid >> 5;
    const int lane = tid & 31;
    const int gi = lane >> 2;
    const int qi = lane & 3;

    const unsigned* Qw = g_qkvh + (size_t)(nh * 3 + 0) * SEQ * 16;
    const uint4* K4 = (const uint4*)(g_qkvh + (size_t)(nh * 3 + 1) * SEQ * 16);
    const unsigned* vTw = g_vTw + (size_t)nh * 32 * (SEQ / 2);

    // per-buffer smem base + ldmatrix addresses
    unsigned sb[2], ka[2], va[2];
    #pragma unroll
    for (int b = 0; b < 2; b++) {
        sb[b] = (unsigned)__cvta_generic_to_shared(&sm[b][0]);
        ka[b] = sb[b] + ((lane & 7) * KS_STR + ((lane >> 3) << 2)) * 4;
        va[b] = sb[b] + KBYTES + ((((lane >> 3) << 3) + (lane & 7)) * VS_STR) * 4;
    }
    const int fk_key = tid >> 2, fk_w4 = tid & 3;
    const int fv_ch = tid >> 4, fv_j4 = tid & 15;

    // prologue: prefetch tile 0
    {
        cpa16(sb[0] + fk_key * 80 + fk_w4 * 16, K4 + fk_key * 4 + fk_w4);
        cpa16(sb[0] + (fk_key + 64) * 80 + fk_w4 * 16, K4 + (fk_key + 64) * 4 + fk_w4);
        cpa16(sb[0] + KBYTES + fv_ch * 272 + fv_j4 * 16,
              vTw + (size_t)fv_ch * (SEQ / 2) + fv_j4 * 4);
        cpa16(sb[0] + KBYTES + (fv_ch + 16) * 272 + fv_j4 * 16,
              vTw + (size_t)(fv_ch + 16) * (SEQ / 2) + fv_j4 * 4);
        cpa_commit();
    }

    // Q fragments (pre-scaled by 1/(sqrt(32)*ln2))
    unsigned qf[2][4];
    {
        const int r0 = qbase + wid * 16 + gi;
        const int r1 = r0 + 8;
        #pragma unroll
        for (int kk = 0; kk < 2; kk++) {
            qf[kk][0] = Qw[(size_t)r0 * 16 + kk * 8 + qi];
            qf[kk][1] = Qw[(size_t)r1 * 16 + kk * 8 + qi];
            qf[kk][2] = Qw[(size_t)r0 * 16 + kk * 8 + qi + 4];
            qf[kk][3] = Qw[(size_t)r1 * 16 + kk * 8 + qi + 4];
        }
    }

    float of[4][4];
    #pragma unroll
    for (int i = 0; i < 4; i++)
        #pragma unroll
        for (int j = 0; j < 4; j++) of[i][j] = 0.0f;
    float of4[4] = {0.f, 0.f, 0.f, 0.f};               // row-sum accumulator
    const unsigned onesb = (gi == 0) ? 0x3F803F80u : 0u;  // B col-of-ones fragment

    for (int t = 0; t < NTILES; t++) {
        if (t + 1 < NTILES) {
            const unsigned d = sb[(t + 1) & 1];
            const int ktn = (t + 1) * KT;
            cpa16(d + fk_key * 80 + fk_w4 * 16, K4 + (ktn + fk_key) * 4 + fk_w4);
            cpa16(d + (fk_key + 64) * 80 + fk_w4 * 16, K4 + (ktn + fk_key + 64) * 4 + fk_w4);
            cpa16(d + KBYTES + fv_ch * 272 + fv_j4 * 16,
                  vTw + (size_t)fv_ch * (SEQ / 2) + (ktn >> 1) + fv_j4 * 4);
            cpa16(d + KBYTES + (fv_ch + 16) * 272 + fv_j4 * 16,
                  vTw + (size_t)(fv_ch + 16) * (SEQ / 2) + (ktn >> 1) + fv_j4 * 4);
        }
        cpa_commit();
        cpa_wait1();
        __syncthreads();

        const unsigned kaddr = ka[t & 1];
        const unsigned vaddr = va[t & 1];
        #pragma unroll
        for (int c = 0; c < 8; c++) {          // staggered 16-key chunks
            const int cc = (c + wid) & 7;      // de-convoy: each warp starts elsewhere
            unsigned kr0[4], kr1[4], vr0[4], vr1[4];
            ldsm_x4(kr0, kaddr + (unsigned)(cc * 16 * KS_STR * 4));
            ldsm_x4(kr1, kaddr + (unsigned)((cc * 16 + 8) * KS_STR * 4));
            ldsm_x4(vr0, vaddr + (unsigned)(cc * 32));
            ldsm_x4(vr1, vaddr + (unsigned)(cc * 32 + 16));

            float s0[4] = {0.f, 0.f, 0.f, 0.f};
            float s1[4] = {0.f, 0.f, 0.f, 0.f};
            mma_bf16(s0, qf[0][0], qf[0][1], qf[0][2], qf[0][3], kr0[0], kr0[1]);
            mma_bf16(s0, qf[1][0], qf[1][1], qf[1][2], qf[1][3], kr0[2], kr0[3]);
            mma_bf16(s1, qf[0][0], qf[0][1], qf[0][2], qf[0][3], kr1[0], kr1[1]);
            mma_bf16(s1, qf[1][0], qf[1][1], qf[1][2], qf[1][3], kr1[2], kr1[3]);

            // pack scores to bf16x2, then one MUFU op per pair
            unsigned pa0 = ex2_bf16x2(pack_bf(s0[0], s0[1]));
            unsigned pa1 = ex2_bf16x2(pack_bf(s0[2], s0[3]));
            unsigned pa2 = ex2_bf16x2(pack_bf(s1[0], s1[1]));
            unsigned pa3 = ex2_bf16x2(pack_bf(s1[2], s1[3]));
            #pragma unroll
            for (int nb = 0; nb < 4; nb++)
                mma_bf16(of[nb], pa0, pa1, pa2, pa3, vr0[nb], vr1[nb]);
            mma_bf16(of4, pa0, pa1, pa2, pa3, onesb, onesb);  // row sums
        }
        __syncthreads();
    }

    // broadcast row sums from each quad's qi==0 lane
    const float l0 = __shfl_sync(0xFFFFFFFFu, of4[0], lane & 28);
    const float l1 = __shfl_sync(0xFFFFFFFFu, of4[2], lane & 28);
    const float il0 = 1.0f / l0;
    const float il1 = 1.0f / l1;

    // stage O through smem for coalesced transposed store
    float* Ob = (float*)sm;                    // [128][36]
    const int r0 = wid * 16 + gi;
    #pragma unroll
    for (int nb = 0; nb < 4; nb++) {
        Ob[r0 * 36 + nb * 8 + 2 * qi]           = of[nb][0] * il0;
        Ob[r0 * 36 + nb * 8 + 2 * qi + 1]       = of[nb][1] * il0;
        Ob[(r0 + 8) * 36 + nb * 8 + 2 * qi]     = of[nb][2] * il1;
        Ob[(r0 + 8) * 36 + nb * 8 + 2 * qi + 1] = of[nb][3] * il1;
    }
    __syncthreads();

    const int n = nh >> 3, h = nh & 7;
    float* outb = g_att + ((size_t)n * 256 + h * 32) * SEQ + qbase;
    #pragma unroll
    for (int u = 0; u < 16; u++) {
        int idx = tid + u * 256;
        int vc = idx >> 7, col = idx & 127;
        outb[(size_t)vc * SEQ + col] = Ob[col * 36 + vc];
    }
}

// ---------------- launch -------------------------------------------------------
extern "C" void kernel_launch(void* const* d_in, const int* in_sizes, int n_in,
                              void* d_out, int out_size) {
    const float* x    = (const float*)d_in[0];  // (2,256,48,48)
    const float* wqkv = (const float*)d_in[1];  // (768,256,1,1)
    const float* wout = (const float*)d_in[2];  // (256,256,1,1)
    float* out = (float*)d_out;                 // (2,256,48,48)

    norm_w_kernel<<<1024, 256>>>(wqkv, wout);
    gemm_qkv_kernel<<<dim3(36, 12, 2), 256>>>(x);
    norm_qkv_kernel<<<864, 256>>>();
    attn_kernel<<<dim3(SEQ / 128, 16), 256>>>();
    gemm_out_kernel<<<dim3(36, 4, 2), 256>>>(out, x);
}